// round 11
// baseline (speedup 1.0000x reference)
#include <cuda_runtime.h>
#include <cuda_fp16.h>
#include <cstdint>

#define N_NODES 50000
#define N_NEXT  2000
#define D       128
#define E_MAX   1600000

#define KB        32
#define NCH_A     63                   // ceil(2000/32)
#define NCH_TOT   67                   // + 128/32 for curr_h phase
#define CHUNK_U32 2048                 // B frags: 2 ks * 16 j * 32 lanes * 2 regs (f16x2)

// ---------------- scratch ----------------
__device__ __half2  g_Hh[(size_t)N_NODES * 64];          // H in fp16
__device__ float    g_Pp[(size_t)N_NEXT * D];
__device__ uint32_t g_BF[(size_t)NCH_TOT * CHUNK_U32];   // B fp16 fragments
__device__ float    g_bias[D];
__device__ int      g_in_cnt[N_NODES];
__device__ int      g_out_cnt[N_NODES];
__device__ int      g_row_ofs[N_NODES + 1];
__device__ int      g_csr_src[E_MAX];
__device__ int      g_blk[64];

// ---------------- helpers ----------------
__device__ __forceinline__ uint32_t smem_u32(const void* p) {
    uint32_t a;
    asm("{ .reg .u64 t; cvta.to.shared.u64 t, %1; cvt.u32.u64 %0, t; }" : "=r"(a) : "l"(p));
    return a;
}
__device__ __forceinline__ void cp16(uint32_t s, const void* g) {
    asm volatile("cp.async.cg.shared.global [%0], [%1], 16;" :: "r"(s), "l"(g) : "memory");
}
__device__ __forceinline__ uint32_t cvt2h(float lo, float hi) {
    uint32_t u;
    asm("cvt.rn.f16x2.f32 %0, %1, %2;" : "=r"(u) : "f"(hi), "f"(lo));  // 2nd src -> lo half
    return u;
}
__device__ __forceinline__ void mma16(float* c, const uint32_t* a, uint32_t b0, uint32_t b1) {
    asm volatile(
        "mma.sync.aligned.m16n8k16.row.col.f32.f16.f16.f32 "
        "{%0,%1,%2,%3}, {%4,%5,%6,%7}, {%8,%9}, {%0,%1,%2,%3};"
        : "+f"(c[0]), "+f"(c[1]), "+f"(c[2]), "+f"(c[3])
        : "r"(a[0]), "r"(a[1]), "r"(a[2]), "r"(a[3]), "r"(b0), "r"(b1));
}
__device__ __forceinline__ int clampi(int v, int lo, int hi) {
    return v < lo ? lo : (v > hi ? hi : v);
}
// acc += H_row[lane*4 .. lane*4+3] (fp16 row)
__device__ __forceinline__ void accH(float4& a, const __half2* rowp, int lane) {
    uint2 u = *reinterpret_cast<const uint2*>(rowp + lane * 2);
    __half2 h0 = *reinterpret_cast<__half2*>(&u.x);
    __half2 h1 = *reinterpret_cast<__half2*>(&u.y);
    float2 f0 = __half22float2(h0);
    float2 f1 = __half22float2(h1);
    a.x += f0.x; a.y += f0.y; a.z += f1.x; a.w += f1.y;
}

// ---------------- CSR build ----------------
__global__ void k_count_out(const int* __restrict__ src, int E) {
    int e4 = (blockIdx.x * blockDim.x + threadIdx.x) * 4;
    if (e4 + 4 <= E) {
        int4 s = *reinterpret_cast<const int4*>(src + e4);
        atomicAdd(&g_out_cnt[clampi(s.x, 0, N_NODES - 1)], 1);
        atomicAdd(&g_out_cnt[clampi(s.y, 0, N_NODES - 1)], 1);
        atomicAdd(&g_out_cnt[clampi(s.z, 0, N_NODES - 1)], 1);
        atomicAdd(&g_out_cnt[clampi(s.w, 0, N_NODES - 1)], 1);
    } else {
        for (int e = e4; e < E; e++)
            atomicAdd(&g_out_cnt[clampi(src[e], 0, N_NODES - 1)], 1);
    }
}
__global__ void k_count_in(const int* __restrict__ dst, int E) {
    int e4 = (blockIdx.x * blockDim.x + threadIdx.x) * 4;
    if (e4 + 4 <= E) {
        int4 d = *reinterpret_cast<const int4*>(dst + e4);
        atomicAdd(&g_in_cnt[clampi(d.x, 0, N_NODES - 1)], 1);
        atomicAdd(&g_in_cnt[clampi(d.y, 0, N_NODES - 1)], 1);
        atomicAdd(&g_in_cnt[clampi(d.z, 0, N_NODES - 1)], 1);
        atomicAdd(&g_in_cnt[clampi(d.w, 0, N_NODES - 1)], 1);
    } else {
        for (int e = e4; e < E; e++)
            atomicAdd(&g_in_cnt[clampi(dst[e], 0, N_NODES - 1)], 1);
    }
}

__global__ void k_scan_a() {
    __shared__ int sh[1024];
    int b = blockIdx.x, t = threadIdx.x, i = b * 1024 + t;
    int v = (i < N_NODES) ? g_in_cnt[i] : 0;
    sh[t] = v;
    __syncthreads();
    for (int off = 1; off < 1024; off <<= 1) {
        int tv = (t >= off) ? sh[t - off] : 0;
        __syncthreads();
        sh[t] += tv;
        __syncthreads();
    }
    if (i < N_NODES) g_row_ofs[i] = sh[t] - v;
    if (t == 1023) g_blk[b] = sh[1023];
}
__global__ void k_scan_b() {
    __shared__ int sh[64];
    int t = threadIdx.x;
    int v = (t < 49) ? g_blk[t] : 0;
    sh[t] = v;
    __syncthreads();
    for (int off = 1; off < 64; off <<= 1) {
        int tv = (t >= off) ? sh[t - off] : 0;
        __syncthreads();
        sh[t] += tv;
        __syncthreads();
    }
    if (t < 49) g_blk[t] = sh[t] - v;
}
__global__ void k_scan_c() {
    int b = blockIdx.x, i = b * 1024 + threadIdx.x;
    if (i < N_NODES && b > 0) g_row_ofs[i] += g_blk[b];
}

// fill uses g_row_ofs itself as cursor; afterwards row_ofs[d] == orig_row_ofs[d+1]
__global__ void k_fill(const int* __restrict__ src, const int* __restrict__ dst, int E) {
    int e4 = (blockIdx.x * blockDim.x + threadIdx.x) * 4;
    if (e4 + 4 <= E) {
        int4 s = *reinterpret_cast<const int4*>(src + e4);
        int4 d = *reinterpret_cast<const int4*>(dst + e4);
        int pos;
        pos = atomicAdd(&g_row_ofs[clampi(d.x, 0, N_NODES - 1)], 1);
        g_csr_src[pos] = clampi(s.x, 0, N_NODES - 1);
        pos = atomicAdd(&g_row_ofs[clampi(d.y, 0, N_NODES - 1)], 1);
        g_csr_src[pos] = clampi(s.y, 0, N_NODES - 1);
        pos = atomicAdd(&g_row_ofs[clampi(d.z, 0, N_NODES - 1)], 1);
        g_csr_src[pos] = clampi(s.z, 0, N_NODES - 1);
        pos = atomicAdd(&g_row_ofs[clampi(d.w, 0, N_NODES - 1)], 1);
        g_csr_src[pos] = clampi(s.w, 0, N_NODES - 1);
    } else {
        for (int e = e4; e < E; e++) {
            int pos = atomicAdd(&g_row_ofs[clampi(dst[e], 0, N_NODES - 1)], 1);
            g_csr_src[pos] = clampi(src[e], 0, N_NODES - 1);
        }
    }
}

// ---------------- prep: Pp = (next_h@W_fus)*tdw ; bias ----------------
__global__ void k_prepP(const float* __restrict__ next_h, const float* __restrict__ W_fus,
                        const float* __restrict__ tdw, const float* __restrict__ b_conv,
                        const float* __restrict__ b_fus, const float* __restrict__ conv_w) {
    __shared__ float sh[16][D];
    int r0 = blockIdx.x * 16;
    int j = threadIdx.x;
    if (blockIdx.x == 0) g_bias[j] = b_conv[j] * conv_w[j] + b_fus[j] * tdw[j];
    #pragma unroll
    for (int r = 0; r < 16; r++) sh[r][j] = next_h[(r0 + r) * D + j];
    __syncthreads();
    float acc[16];
    #pragma unroll
    for (int r = 0; r < 16; r++) acc[r] = 0.f;
    for (int k = 0; k < D; k++) {
        float w = W_fus[k * D + j];
        #pragma unroll
        for (int r = 0; r < 16; r++) acc[r] += sh[r][k] * w;
    }
    float t = tdw[j];
    #pragma unroll
    for (int r = 0; r < 16; r++) g_Pp[(size_t)(r0 + r) * D + j] = acc[r] * t;
}

// pack B into m16n8k16 fp16 fragment order, one 8KB chunk per K-block of 32.
__global__ void k_packB(const float* __restrict__ W_conv, const float* __restrict__ conv_w) {
    int i = blockIdx.x * blockDim.x + threadIdx.x;
    if (i >= NCH_TOT * CHUNK_U32) return;
    int c = i >> 11, rem = i & 2047;
    int e = rem & 1;
    int lane = (rem >> 1) & 31;
    int j = (rem >> 6) & 15;
    int ks = rem >> 10;
    int g = lane >> 2, tg = lane & 3;
    int n = j * 8 + g;
    int kl = ks * 16 + 2 * tg + e * 8;
    float v0, v1;
    if (c < NCH_A) {
        int kg = c * KB + kl;
        v0 = (kg < N_NEXT) ? g_Pp[(size_t)kg * D + n] : 0.f;
        v1 = (kg + 1 < N_NEXT) ? g_Pp[(size_t)(kg + 1) * D + n] : 0.f;
    } else {
        int kg = (c - NCH_A) * KB + kl;
        v0 = W_conv[kg * D + n] * conv_w[n];
        v1 = W_conv[(kg + 1) * D + n] * conv_w[n];
    }
    g_BF[i] = cvt2h(v0, v1);
}

// ---------------- fp16 mma GEMM: H = inc@Pp + curr_h@Wcp -> fp16 (un-normalized) ----------------
// 256 threads (8 warps), M=128 (16 rows/warp), N=128, K-chunk 32, 3-stage pipeline.
#define ASTRIDE 40
#define A_TILE_F (128 * ASTRIDE)
#define NSTAGE 3
__global__ __launch_bounds__(256, 2) void k_gemm(const float* __restrict__ curr_h,
                                                 const float* __restrict__ inc) {
    extern __shared__ char smem[];
    float*    sA = reinterpret_cast<float*>(smem);                             // [3][128*40]
    uint32_t* sB = reinterpret_cast<uint32_t*>(smem + NSTAGE * A_TILE_F * 4);  // [3][2048]
    const int tid = threadIdx.x, wid = tid >> 5, lane = tid & 31;
    const int g = lane >> 2, tg = lane & 3;
    const int bm = blockIdx.x * 128;

    float acc[16][4];
    #pragma unroll
    for (int j = 0; j < 16; j++)
        #pragma unroll
        for (int q = 0; q < 4; q++) acc[j][q] = 0.f;

    auto fetch = [&](int c, int buf) {
        const float* Ap; int ld, k0;
        if (c < NCH_A) { Ap = inc; ld = N_NEXT; k0 = c * KB; }
        else           { Ap = curr_h; ld = D; k0 = (c - NCH_A) * KB; }
        #pragma unroll
        for (int q8 = 0; q8 < 4; q8++) {
            int idx = q8 * 256 + tid;
            int row = idx >> 3, quad = idx & 7;
            int grow = bm + row;
            if (grow >= N_NODES) grow = N_NODES - 1;
            int col = k0 + quad * 4;
            float* dstp = sA + buf * A_TILE_F + row * ASTRIDE + quad * 4;
            if (col + 4 <= ld) cp16(smem_u32(dstp), Ap + (size_t)grow * ld + col);
            else *reinterpret_cast<float4*>(dstp) = make_float4(0.f, 0.f, 0.f, 0.f);
        }
        const uint32_t* srcb = g_BF + (size_t)c * CHUNK_U32 + tid * 8;
        uint32_t dstb = smem_u32(sB + buf * CHUNK_U32 + tid * 8);
        cp16(dstb, srcb); cp16(dstb + 16, srcb + 4);
        asm volatile("cp.async.commit_group;" ::: "memory");
    };

    auto compute = [&](int buf) {
        const float* sa = sA + buf * A_TILE_F;
        const uint32_t* sb = sB + buf * CHUNK_U32;
        #pragma unroll
        for (int ks = 0; ks < 2; ks++) {
            const float* base = sa + wid * 16 * ASTRIDE + ks * 16 + 2 * tg;
            float2 p0 = *reinterpret_cast<const float2*>(base + g * ASTRIDE);
            float2 p1 = *reinterpret_cast<const float2*>(base + (g + 8) * ASTRIDE);
            float2 p2 = *reinterpret_cast<const float2*>(base + g * ASTRIDE + 8);
            float2 p3 = *reinterpret_cast<const float2*>(base + (g + 8) * ASTRIDE + 8);
            uint32_t af[4];
            af[0] = cvt2h(p0.x, p0.y);
            af[1] = cvt2h(p1.x, p1.y);
            af[2] = cvt2h(p2.x, p2.y);
            af[3] = cvt2h(p3.x, p3.y);
            #pragma unroll
            for (int j = 0; j < 16; j++) {
                uint2 b = *reinterpret_cast<const uint2*>(sb + (ks * 16 + j) * 64 + lane * 2);
                mma16(acc[j], af, b.x, b.y);
            }
        }
    };

    fetch(0, 0);
    fetch(1, 1);
    int buf = 0;
    for (int c = 0; c < NCH_TOT; ++c) {
        if (c + 2 < NCH_TOT) {
            int nb = buf + 2; if (nb >= NSTAGE) nb -= NSTAGE;
            fetch(c + 2, nb);
            asm volatile("cp.async.wait_group 2;" ::: "memory");
        } else if (c + 1 < NCH_TOT) {
            asm volatile("cp.async.wait_group 1;" ::: "memory");
        } else {
            asm volatile("cp.async.wait_group 0;" ::: "memory");
        }
        __syncthreads();
        compute(buf);
        __syncthreads();
        if (++buf == NSTAGE) buf = 0;
    }

    // epilogue: write fp16 H (norm_out applied by k_normH)
    int r0 = bm + wid * 16 + g;
    int r1 = r0 + 8;
    if (r0 < N_NODES) {
        __half2* dp = g_Hh + (size_t)r0 * 64 + tg;
        #pragma unroll
        for (int j = 0; j < 16; j++)
            dp[j * 4] = __floats2half2_rn(acc[j][0], acc[j][1]);
    }
    if (r1 < N_NODES) {
        __half2* dp = g_Hh + (size_t)r1 * 64 + tg;
        #pragma unroll
        for (int j = 0; j < 16; j++)
            dp[j * 4] = __floats2half2_rn(acc[j][2], acc[j][3]);
    }
}
#define GEMM_SMEM (NSTAGE * (A_TILE_F * 4 + CHUNK_U32 * 4))

// ---------------- normalize H rows by rsqrt(out_deg+1) ----------------
// one warp per row; lane handles 2 half2 (4 values)
__global__ void k_normH() {
    int warp = (blockIdx.x * blockDim.x + threadIdx.x) >> 5;
    int lane = threadIdx.x & 31;
    if (warp >= N_NODES) return;
    float no = rsqrtf((float)(__ldg(g_out_cnt + warp) + 1));
    __half2* rowp = g_Hh + (size_t)warp * 64 + lane * 2;
    uint2 u = *reinterpret_cast<uint2*>(rowp);
    __half2 h0 = *reinterpret_cast<__half2*>(&u.x);
    __half2 h1 = *reinterpret_cast<__half2*>(&u.y);
    float2 f0 = __half22float2(h0);
    float2 f1 = __half22float2(h1);
    uint2 o;
    o.x = cvt2h(f0.x * no, f0.y * no);
    o.y = cvt2h(f1.x * no, f1.y * no);
    *reinterpret_cast<uint2*>(rowp) = o;
}

// ---------------- gather + norm_in + bias + LayerNorm + ReLU ----------------
// note: g_row_ofs was mutated by k_fill: row_ofs[d] == original row_ofs[d+1]
__global__ void k_gather(const float* __restrict__ ln_g, const float* __restrict__ ln_b,
                         float* __restrict__ out) {
    int warp = (blockIdx.x * blockDim.x + threadIdx.x) >> 5;
    int lane = threadIdx.x & 31;
    if (warp >= N_NODES) return;

    float4 av[8];
    #pragma unroll
    for (int q = 0; q < 8; q++) av[q] = make_float4(0.f, 0.f, 0.f, 0.f);
    accH(av[0], g_Hh + (size_t)warp * 64, lane);       // self-loop
    int beg = (warp == 0) ? 0 : __ldg(g_row_ofs + warp - 1);
    int end = __ldg(g_row_ofs + warp);

    int j = beg;
    for (; j + 8 <= end; j += 8) {
        int sv[8];
        #pragma unroll
        for (int q = 0; q < 8; q++) sv[q] = __ldg(g_csr_src + j + q);
        #pragma unroll
        for (int q = 0; q < 8; q++) accH(av[q], g_Hh + (size_t)sv[q] * 64, lane);
    }
    for (; j < end; j++) {
        int s = __ldg(g_csr_src + j);
        accH(av[0], g_Hh + (size_t)s * 64, lane);
    }
    float4 acc;
    acc.x = ((av[0].x + av[1].x) + (av[2].x + av[3].x)) + ((av[4].x + av[5].x) + (av[6].x + av[7].x));
    acc.y = ((av[0].y + av[1].y) + (av[2].y + av[3].y)) + ((av[4].y + av[5].y) + (av[6].y + av[7].y));
    acc.z = ((av[0].z + av[1].z) + (av[2].z + av[3].z)) + ((av[4].z + av[5].z) + (av[6].z + av[7].z));
    acc.w = ((av[0].w + av[1].w) + (av[2].w + av[3].w)) + ((av[4].w + av[5].w) + (av[6].w + av[7].w));

    float ni = rsqrtf((float)(end - beg + 1));
    int c0 = lane * 4;
    float x0 = acc.x * ni + g_bias[c0 + 0];
    float x1 = acc.y * ni + g_bias[c0 + 1];
    float x2 = acc.z * ni + g_bias[c0 + 2];
    float x3 = acc.w * ni + g_bias[c0 + 3];

    float s = x0 + x1 + x2 + x3;
    #pragma unroll
    for (int off = 16; off > 0; off >>= 1) s += __shfl_xor_sync(0xffffffffu, s, off);
    float mu = s * (1.0f / D);
    float d0 = x0 - mu, d1 = x1 - mu, d2 = x2 - mu, d3 = x3 - mu;
    float q = d0 * d0 + d1 * d1 + d2 * d2 + d3 * d3;
    #pragma unroll
    for (int off = 16; off > 0; off >>= 1) q += __shfl_xor_sync(0xffffffffu, q, off);
    float inv = rsqrtf(q * (1.0f / D) + 1e-5f);

    float4 o;
    o.x = fmaxf(d0 * inv * ln_g[c0 + 0] + ln_b[c0 + 0], 0.f);
    o.y = fmaxf(d1 * inv * ln_g[c0 + 1] + ln_b[c0 + 1], 0.f);
    o.z = fmaxf(d2 * inv * ln_g[c0 + 2] + ln_b[c0 + 2], 0.f);
    o.w = fmaxf(d3 * inv * ln_g[c0 + 3] + ln_b[c0 + 3], 0.f);
    reinterpret_cast<float4*>(out + (size_t)warp * D)[lane] = o;
}

// ---------------- launcher (forked-stream graph) ----------------
extern "C" void kernel_launch(void* const* d_in, const int* in_sizes, int n_in,
                              void* d_out, int out_size) {
    const float* curr_h = (const float*)d_in[0];
    const float* next_h = (const float*)d_in[1];
    const float* inc    = (const float*)d_in[2];
    const int*   src    = (const int*)d_in[3];
    const int*   dst    = (const int*)d_in[4];
    const float* W_conv = (const float*)d_in[5];
    const float* b_conv = (const float*)d_in[6];
    const float* W_fus  = (const float*)d_in[7];
    const float* b_fus  = (const float*)d_in[8];
    const float* conv_w = (const float*)d_in[9];
    const float* tdw    = (const float*)d_in[10];
    const float* ln_g   = (const float*)d_in[11];
    const float* ln_b   = (const float*)d_in[12];
    float* out = (float*)d_out;
    const int E = in_sizes[3];

    static cudaStream_t s1 = nullptr, s2 = nullptr;
    static cudaEvent_t evRoot, evOut, evCsr, evGemm;
    static void *p_in, *p_out;
    if (!s1) {
        cudaStreamCreateWithFlags(&s1, cudaStreamNonBlocking);
        cudaStreamCreateWithFlags(&s2, cudaStreamNonBlocking);
        cudaEventCreateWithFlags(&evRoot, cudaEventDisableTiming);
        cudaEventCreateWithFlags(&evOut, cudaEventDisableTiming);
        cudaEventCreateWithFlags(&evCsr, cudaEventDisableTiming);
        cudaEventCreateWithFlags(&evGemm, cudaEventDisableTiming);
        cudaFuncSetAttribute(k_gemm, cudaFuncAttributeMaxDynamicSharedMemorySize, GEMM_SMEM);
        cudaGetSymbolAddress(&p_in, g_in_cnt);
        cudaGetSymbolAddress(&p_out, g_out_cnt);
    }

    // fork both worker streams off the (captured) default stream
    cudaEventRecord(evRoot, 0);
    cudaStreamWaitEvent(s1, evRoot, 0);
    cudaStreamWaitEvent(s2, evRoot, 0);

    // --- chain 2: dense path, fully independent of CSR ---
    k_prepP<<<N_NEXT / 16, 128, 0, s2>>>(next_h, W_fus, tdw, b_conv, b_fus, conv_w);
    k_packB<<<(NCH_TOT * CHUNK_U32 + 255) / 256, 256, 0, s2>>>(W_conv, conv_w);
    k_gemm<<<(N_NODES + 127) / 128, 256, GEMM_SMEM, s2>>>(curr_h, inc);

    // --- chain 1: CSR build ---
    cudaMemsetAsync(p_out, 0, N_NODES * sizeof(int), s1);
    k_count_out<<<(E / 4 + 255) / 256, 256, 0, s1>>>(src, E);
    cudaEventRecord(evOut, s1);
    cudaMemsetAsync(p_in, 0, N_NODES * sizeof(int), s1);
    k_count_in<<<(E / 4 + 255) / 256, 256, 0, s1>>>(dst, E);
    k_scan_a<<<49, 1024, 0, s1>>>();
    k_scan_b<<<1, 64, 0, s1>>>();
    k_scan_c<<<49, 1024, 0, s1>>>();
    k_fill<<<(E / 4 + 255) / 256, 256, 0, s1>>>(src, dst, E);
    cudaEventRecord(evCsr, s1);

    // --- chain 2 tail: normalize H (needs out-degrees, ready long before) ---
    cudaStreamWaitEvent(s2, evOut, 0);
    k_normH<<<(N_NODES * 32 + 255) / 256, 256, 0, s2>>>();
    cudaEventRecord(evGemm, s2);

    // --- join on default stream, then gather ---
    cudaStreamWaitEvent(0, evCsr, 0);
    cudaStreamWaitEvent(0, evGemm, 0);
    k_gather<<<(N_NODES * 32 + 255) / 256, 256>>>(ln_g, ln_b, out);
}

// round 12
// speedup vs baseline: 1.1090x; 1.1090x over previous
#include <cuda_runtime.h>
#include <cuda_fp16.h>
#include <cstdint>

#define N_NODES 50000
#define N_NEXT  2000
#define D       128
#define E_MAX   1600000

#define KB        32
#define NCH_A     63                   // ceil(2000/32)
#define NCH_TOT   67                   // + 128/32 for curr_h phase
#define CHUNK_U32 2048                 // B frags: 2 ks * 16 j * 32 lanes * 2 regs (f16x2)

// ---------------- scratch ----------------
__device__ __half2  g_Hh[(size_t)N_NODES * 64];          // H in fp16 (normalized)
__device__ float    g_Pp[(size_t)N_NEXT * D];
__device__ uint32_t g_BF[(size_t)NCH_TOT * CHUNK_U32];   // B fp16 fragments
__device__ float    g_bias[D];
__device__ int      g_in_cnt[N_NODES];
__device__ int      g_out_cnt[N_NODES];
__device__ int      g_row_ofs[N_NODES + 1];
__device__ int      g_csr_src[E_MAX];
__device__ int      g_blk[64];

// ---------------- helpers ----------------
__device__ __forceinline__ uint32_t smem_u32(const void* p) {
    uint32_t a;
    asm("{ .reg .u64 t; cvta.to.shared.u64 t, %1; cvt.u32.u64 %0, t; }" : "=r"(a) : "l"(p));
    return a;
}
__device__ __forceinline__ void cp16(uint32_t s, const void* g) {
    asm volatile("cp.async.cg.shared.global [%0], [%1], 16;" :: "r"(s), "l"(g) : "memory");
}
__device__ __forceinline__ uint32_t cvt2h(float lo, float hi) {
    uint32_t u;
    asm("cvt.rn.f16x2.f32 %0, %1, %2;" : "=r"(u) : "f"(hi), "f"(lo));  // 2nd src -> lo half
    return u;
}
__device__ __forceinline__ void mma16(float* c, const uint32_t* a, uint32_t b0, uint32_t b1) {
    asm volatile(
        "mma.sync.aligned.m16n8k16.row.col.f32.f16.f16.f32 "
        "{%0,%1,%2,%3}, {%4,%5,%6,%7}, {%8,%9}, {%0,%1,%2,%3};"
        : "+f"(c[0]), "+f"(c[1]), "+f"(c[2]), "+f"(c[3])
        : "r"(a[0]), "r"(a[1]), "r"(a[2]), "r"(a[3]), "r"(b0), "r"(b1));
}
__device__ __forceinline__ int clampi(int v, int lo, int hi) {
    return v < lo ? lo : (v > hi ? hi : v);
}
// acc += H_row[lane*4 .. lane*4+3] (fp16 row)
__device__ __forceinline__ void accH(float4& a, const __half2* rowp, int lane) {
    uint2 u = *reinterpret_cast<const uint2*>(rowp + lane * 2);
    __half2 h0 = *reinterpret_cast<__half2*>(&u.x);
    __half2 h1 = *reinterpret_cast<__half2*>(&u.y);
    float2 f0 = __half22float2(h0);
    float2 f1 = __half22float2(h1);
    a.x += f0.x; a.y += f0.y; a.z += f1.x; a.w += f1.y;
}

// ---------------- CSR build ----------------
__global__ void k_count_out(const int* __restrict__ src, int E) {
    int e4 = (blockIdx.x * blockDim.x + threadIdx.x) * 4;
    if (e4 + 4 <= E) {
        int4 s = *reinterpret_cast<const int4*>(src + e4);
        atomicAdd(&g_out_cnt[clampi(s.x, 0, N_NODES - 1)], 1);
        atomicAdd(&g_out_cnt[clampi(s.y, 0, N_NODES - 1)], 1);
        atomicAdd(&g_out_cnt[clampi(s.z, 0, N_NODES - 1)], 1);
        atomicAdd(&g_out_cnt[clampi(s.w, 0, N_NODES - 1)], 1);
    } else {
        for (int e = e4; e < E; e++)
            atomicAdd(&g_out_cnt[clampi(src[e], 0, N_NODES - 1)], 1);
    }
}
__global__ void k_count_in(const int* __restrict__ dst, int E) {
    int e4 = (blockIdx.x * blockDim.x + threadIdx.x) * 4;
    if (e4 + 4 <= E) {
        int4 d = *reinterpret_cast<const int4*>(dst + e4);
        atomicAdd(&g_in_cnt[clampi(d.x, 0, N_NODES - 1)], 1);
        atomicAdd(&g_in_cnt[clampi(d.y, 0, N_NODES - 1)], 1);
        atomicAdd(&g_in_cnt[clampi(d.z, 0, N_NODES - 1)], 1);
        atomicAdd(&g_in_cnt[clampi(d.w, 0, N_NODES - 1)], 1);
    } else {
        for (int e = e4; e < E; e++)
            atomicAdd(&g_in_cnt[clampi(dst[e], 0, N_NODES - 1)], 1);
    }
}

__global__ void k_scan_a() {
    __shared__ int sh[1024];
    int b = blockIdx.x, t = threadIdx.x, i = b * 1024 + t;
    int v = (i < N_NODES) ? g_in_cnt[i] : 0;
    sh[t] = v;
    __syncthreads();
    for (int off = 1; off < 1024; off <<= 1) {
        int tv = (t >= off) ? sh[t - off] : 0;
        __syncthreads();
        sh[t] += tv;
        __syncthreads();
    }
    if (i < N_NODES) g_row_ofs[i] = sh[t] - v;
    if (t == 1023) g_blk[b] = sh[1023];
}
__global__ void k_scan_b() {
    __shared__ int sh[64];
    int t = threadIdx.x;
    int v = (t < 49) ? g_blk[t] : 0;
    sh[t] = v;
    __syncthreads();
    for (int off = 1; off < 64; off <<= 1) {
        int tv = (t >= off) ? sh[t - off] : 0;
        __syncthreads();
        sh[t] += tv;
        __syncthreads();
    }
    if (t < 49) g_blk[t] = sh[t] - v;
}
__global__ void k_scan_c() {
    int b = blockIdx.x, i = b * 1024 + threadIdx.x;
    if (i < N_NODES && b > 0) g_row_ofs[i] += g_blk[b];
}

// fill uses g_row_ofs itself as cursor; afterwards row_ofs[d] == orig_row_ofs[d+1]
__global__ void k_fill(const int* __restrict__ src, const int* __restrict__ dst, int E) {
    int e4 = (blockIdx.x * blockDim.x + threadIdx.x) * 4;
    if (e4 + 4 <= E) {
        int4 s = *reinterpret_cast<const int4*>(src + e4);
        int4 d = *reinterpret_cast<const int4*>(dst + e4);
        int pos;
        pos = atomicAdd(&g_row_ofs[clampi(d.x, 0, N_NODES - 1)], 1);
        g_csr_src[pos] = clampi(s.x, 0, N_NODES - 1);
        pos = atomicAdd(&g_row_ofs[clampi(d.y, 0, N_NODES - 1)], 1);
        g_csr_src[pos] = clampi(s.y, 0, N_NODES - 1);
        pos = atomicAdd(&g_row_ofs[clampi(d.z, 0, N_NODES - 1)], 1);
        g_csr_src[pos] = clampi(s.z, 0, N_NODES - 1);
        pos = atomicAdd(&g_row_ofs[clampi(d.w, 0, N_NODES - 1)], 1);
        g_csr_src[pos] = clampi(s.w, 0, N_NODES - 1);
    } else {
        for (int e = e4; e < E; e++) {
            int pos = atomicAdd(&g_row_ofs[clampi(dst[e], 0, N_NODES - 1)], 1);
            g_csr_src[pos] = clampi(src[e], 0, N_NODES - 1);
        }
    }
}

// ---------------- prep: Pp = (next_h@W_fus)*tdw ; bias ----------------
__global__ void k_prepP(const float* __restrict__ next_h, const float* __restrict__ W_fus,
                        const float* __restrict__ tdw, const float* __restrict__ b_conv,
                        const float* __restrict__ b_fus, const float* __restrict__ conv_w) {
    __shared__ float sh[16][D];
    int r0 = blockIdx.x * 16;
    int j = threadIdx.x;
    if (blockIdx.x == 0) g_bias[j] = b_conv[j] * conv_w[j] + b_fus[j] * tdw[j];
    #pragma unroll
    for (int r = 0; r < 16; r++) sh[r][j] = next_h[(r0 + r) * D + j];
    __syncthreads();
    float acc[16];
    #pragma unroll
    for (int r = 0; r < 16; r++) acc[r] = 0.f;
    for (int k = 0; k < D; k++) {
        float w = W_fus[k * D + j];
        #pragma unroll
        for (int r = 0; r < 16; r++) acc[r] += sh[r][k] * w;
    }
    float t = tdw[j];
    #pragma unroll
    for (int r = 0; r < 16; r++) g_Pp[(size_t)(r0 + r) * D + j] = acc[r] * t;
}

// pack B into m16n8k16 fp16 fragment order, one 8KB chunk per K-block of 32.
__global__ void k_packB(const float* __restrict__ W_conv, const float* __restrict__ conv_w) {
    int i = blockIdx.x * blockDim.x + threadIdx.x;
    if (i >= NCH_TOT * CHUNK_U32) return;
    int c = i >> 11, rem = i & 2047;
    int e = rem & 1;
    int lane = (rem >> 1) & 31;
    int j = (rem >> 6) & 15;
    int ks = rem >> 10;
    int g = lane >> 2, tg = lane & 3;
    int n = j * 8 + g;
    int kl = ks * 16 + 2 * tg + e * 8;
    float v0, v1;
    if (c < NCH_A) {
        int kg = c * KB + kl;
        v0 = (kg < N_NEXT) ? g_Pp[(size_t)kg * D + n] : 0.f;
        v1 = (kg + 1 < N_NEXT) ? g_Pp[(size_t)(kg + 1) * D + n] : 0.f;
    } else {
        int kg = (c - NCH_A) * KB + kl;
        v0 = W_conv[kg * D + n] * conv_w[n];
        v1 = W_conv[(kg + 1) * D + n] * conv_w[n];
    }
    g_BF[i] = cvt2h(v0, v1);
}

// ---------------- fp16 mma GEMM: H = norm_out .* (inc@Pp + curr_h@Wcp) -> fp16 ----------------
// 256 threads (8 warps), warp tile 32M x 64N (warp grid 4x2), K-chunk 32, 3-stage pipeline.
#define ASTRIDE 40
#define A_TILE_F (128 * ASTRIDE)
#define NSTAGE 3
__global__ __launch_bounds__(256, 2) void k_gemm(const float* __restrict__ curr_h,
                                                 const float* __restrict__ inc) {
    extern __shared__ char smem[];
    float*    sA = reinterpret_cast<float*>(smem);                             // [3][128*40]
    uint32_t* sB = reinterpret_cast<uint32_t*>(smem + NSTAGE * A_TILE_F * 4);  // [3][2048]
    const int tid = threadIdx.x, wid = tid >> 5, lane = tid & 31;
    const int g = lane >> 2, tg = lane & 3;
    const int mw = wid & 3, nw = wid >> 2;     // 4 M-slabs x 2 N-halves
    const int bm = blockIdx.x * 128;

    float acc[2][8][4];
    #pragma unroll
    for (int mt = 0; mt < 2; mt++)
        #pragma unroll
        for (int j = 0; j < 8; j++)
            #pragma unroll
            for (int q = 0; q < 4; q++) acc[mt][j][q] = 0.f;

    auto fetch = [&](int c, int buf) {
        const float* Ap; int ld, k0;
        if (c < NCH_A) { Ap = inc; ld = N_NEXT; k0 = c * KB; }
        else           { Ap = curr_h; ld = D; k0 = (c - NCH_A) * KB; }
        #pragma unroll
        for (int q8 = 0; q8 < 4; q8++) {
            int idx = q8 * 256 + tid;
            int row = idx >> 3, quad = idx & 7;
            int grow = bm + row;
            if (grow >= N_NODES) grow = N_NODES - 1;
            int col = k0 + quad * 4;
            float* dstp = sA + buf * A_TILE_F + row * ASTRIDE + quad * 4;
            if (col + 4 <= ld) cp16(smem_u32(dstp), Ap + (size_t)grow * ld + col);
            else *reinterpret_cast<float4*>(dstp) = make_float4(0.f, 0.f, 0.f, 0.f);
        }
        const uint32_t* srcb = g_BF + (size_t)c * CHUNK_U32 + tid * 8;
        uint32_t dstb = smem_u32(sB + buf * CHUNK_U32 + tid * 8);
        cp16(dstb, srcb); cp16(dstb + 16, srcb + 4);
        asm volatile("cp.async.commit_group;" ::: "memory");
    };

    auto compute = [&](int buf) {
        const float* sa = sA + buf * A_TILE_F;
        const uint32_t* sb = sB + buf * CHUNK_U32;
        #pragma unroll
        for (int ks = 0; ks < 2; ks++) {
            uint32_t af[2][4];
            #pragma unroll
            for (int mt = 0; mt < 2; mt++) {
                const float* base = sa + (mw * 32 + mt * 16) * ASTRIDE + ks * 16 + 2 * tg;
                float2 p0 = *reinterpret_cast<const float2*>(base + g * ASTRIDE);
                float2 p1 = *reinterpret_cast<const float2*>(base + (g + 8) * ASTRIDE);
                float2 p2 = *reinterpret_cast<const float2*>(base + g * ASTRIDE + 8);
                float2 p3 = *reinterpret_cast<const float2*>(base + (g + 8) * ASTRIDE + 8);
                af[mt][0] = cvt2h(p0.x, p0.y);
                af[mt][1] = cvt2h(p1.x, p1.y);
                af[mt][2] = cvt2h(p2.x, p2.y);
                af[mt][3] = cvt2h(p3.x, p3.y);
            }
            #pragma unroll
            for (int j = 0; j < 8; j++) {
                uint2 b = *reinterpret_cast<const uint2*>(
                    sb + (ks * 16 + nw * 8 + j) * 64 + lane * 2);
                mma16(acc[0][j], af[0], b.x, b.y);
                mma16(acc[1][j], af[1], b.x, b.y);
            }
        }
    };

    fetch(0, 0);
    fetch(1, 1);
    int buf = 0;
    for (int c = 0; c < NCH_TOT; ++c) {
        if (c + 2 < NCH_TOT) {
            int nb = buf + 2; if (nb >= NSTAGE) nb -= NSTAGE;
            fetch(c + 2, nb);
            asm volatile("cp.async.wait_group 2;" ::: "memory");
        } else if (c + 1 < NCH_TOT) {
            asm volatile("cp.async.wait_group 1;" ::: "memory");
        } else {
            asm volatile("cp.async.wait_group 0;" ::: "memory");
        }
        __syncthreads();
        compute(buf);
        __syncthreads();
        if (++buf == NSTAGE) buf = 0;
    }

    // epilogue: apply norm_out, convert to fp16, write H (cols nw*64 .. nw*64+63)
    #pragma unroll
    for (int mt = 0; mt < 2; mt++) {
        int r0 = bm + mw * 32 + mt * 16 + g;
        int r1 = r0 + 8;
        if (r0 < N_NODES) {
            float no = rsqrtf((float)(g_out_cnt[r0] + 1));
            __half2* dp = g_Hh + (size_t)r0 * 64 + nw * 32 + tg;
            #pragma unroll
            for (int j = 0; j < 8; j++)
                dp[j * 4] = __floats2half2_rn(acc[mt][j][0] * no, acc[mt][j][1] * no);
        }
        if (r1 < N_NODES) {
            float no = rsqrtf((float)(g_out_cnt[r1] + 1));
            __half2* dp = g_Hh + (size_t)r1 * 64 + nw * 32 + tg;
            #pragma unroll
            for (int j = 0; j < 8; j++)
                dp[j * 4] = __floats2half2_rn(acc[mt][j][2] * no, acc[mt][j][3] * no);
        }
    }
}
#define GEMM_SMEM (NSTAGE * (A_TILE_F * 4 + CHUNK_U32 * 4))

// ---------------- gather + norm_in + bias + LayerNorm + ReLU ----------------
// note: g_row_ofs was mutated by k_fill: row_ofs[d] == original row_ofs[d+1]
__global__ void k_gather(const float* __restrict__ ln_g, const float* __restrict__ ln_b,
                         float* __restrict__ out) {
    int warp = (blockIdx.x * blockDim.x + threadIdx.x) >> 5;
    int lane = threadIdx.x & 31;
    if (warp >= N_NODES) return;

    float4 a0 = make_float4(0.f, 0.f, 0.f, 0.f), a1 = a0, a2 = a0, a3 = a0;
    accH(a0, g_Hh + (size_t)warp * 64, lane);       // self-loop
    int beg = (warp == 0) ? 0 : __ldg(g_row_ofs + warp - 1);
    int end = __ldg(g_row_ofs + warp);

    int j = beg;
    for (; j + 4 <= end; j += 4) {
        int s0 = __ldg(g_csr_src + j);
        int s1 = __ldg(g_csr_src + j + 1);
        int s2 = __ldg(g_csr_src + j + 2);
        int s3 = __ldg(g_csr_src + j + 3);
        accH(a0, g_Hh + (size_t)s0 * 64, lane);
        accH(a1, g_Hh + (size_t)s1 * 64, lane);
        accH(a2, g_Hh + (size_t)s2 * 64, lane);
        accH(a3, g_Hh + (size_t)s3 * 64, lane);
    }
    for (; j < end; j++) {
        int s = __ldg(g_csr_src + j);
        accH(a0, g_Hh + (size_t)s * 64, lane);
    }
    float4 acc;
    acc.x = (a0.x + a1.x) + (a2.x + a3.x);
    acc.y = (a0.y + a1.y) + (a2.y + a3.y);
    acc.z = (a0.z + a1.z) + (a2.z + a3.z);
    acc.w = (a0.w + a1.w) + (a2.w + a3.w);

    float ni = rsqrtf((float)(end - beg + 1));
    int c0 = lane * 4;
    float x0 = acc.x * ni + g_bias[c0 + 0];
    float x1 = acc.y * ni + g_bias[c0 + 1];
    float x2 = acc.z * ni + g_bias[c0 + 2];
    float x3 = acc.w * ni + g_bias[c0 + 3];

    float s = x0 + x1 + x2 + x3;
    #pragma unroll
    for (int off = 16; off > 0; off >>= 1) s += __shfl_xor_sync(0xffffffffu, s, off);
    float mu = s * (1.0f / D);
    float d0 = x0 - mu, d1 = x1 - mu, d2 = x2 - mu, d3 = x3 - mu;
    float q = d0 * d0 + d1 * d1 + d2 * d2 + d3 * d3;
    #pragma unroll
    for (int off = 16; off > 0; off >>= 1) q += __shfl_xor_sync(0xffffffffu, q, off);
    float inv = rsqrtf(q * (1.0f / D) + 1e-5f);

    float4 o;
    o.x = fmaxf(d0 * inv * ln_g[c0 + 0] + ln_b[c0 + 0], 0.f);
    o.y = fmaxf(d1 * inv * ln_g[c0 + 1] + ln_b[c0 + 1], 0.f);
    o.z = fmaxf(d2 * inv * ln_g[c0 + 2] + ln_b[c0 + 2], 0.f);
    o.w = fmaxf(d3 * inv * ln_g[c0 + 3] + ln_b[c0 + 3], 0.f);
    reinterpret_cast<float4*>(out + (size_t)warp * D)[lane] = o;
}

// ---------------- launcher (forked-stream graph; gemm is 4th submitted kernel) ----------------
extern "C" void kernel_launch(void* const* d_in, const int* in_sizes, int n_in,
                              void* d_out, int out_size) {
    const float* curr_h = (const float*)d_in[0];
    const float* next_h = (const float*)d_in[1];
    const float* inc    = (const float*)d_in[2];
    const int*   src    = (const int*)d_in[3];
    const int*   dst    = (const int*)d_in[4];
    const float* W_conv = (const float*)d_in[5];
    const float* b_conv = (const float*)d_in[6];
    const float* W_fus  = (const float*)d_in[7];
    const float* b_fus  = (const float*)d_in[8];
    const float* conv_w = (const float*)d_in[9];
    const float* tdw    = (const float*)d_in[10];
    const float* ln_g   = (const float*)d_in[11];
    const float* ln_b   = (const float*)d_in[12];
    float* out = (float*)d_out;
    const int E = in_sizes[3];

    static cudaStream_t s1 = nullptr, s2 = nullptr;
    static cudaEvent_t evRoot, evOut, evCsr, evGemm;
    static void *p_in, *p_out;
    if (!s1) {
        cudaStreamCreateWithFlags(&s1, cudaStreamNonBlocking);
        cudaStreamCreateWithFlags(&s2, cudaStreamNonBlocking);
        cudaEventCreateWithFlags(&evRoot, cudaEventDisableTiming);
        cudaEventCreateWithFlags(&evOut, cudaEventDisableTiming);
        cudaEventCreateWithFlags(&evCsr, cudaEventDisableTiming);
        cudaEventCreateWithFlags(&evGemm, cudaEventDisableTiming);
        cudaFuncSetAttribute(k_gemm, cudaFuncAttributeMaxDynamicSharedMemorySize, GEMM_SMEM);
        cudaGetSymbolAddress(&p_in, g_in_cnt);
        cudaGetSymbolAddress(&p_out, g_out_cnt);
    }

    // fork both worker streams off the (captured) default stream
    cudaEventRecord(evRoot, 0);
    cudaStreamWaitEvent(s1, evRoot, 0);
    cudaStreamWaitEvent(s2, evRoot, 0);

    // kernel #1: out-degree (GEMM epilogue dependency)
    cudaMemsetAsync(p_out, 0, N_NODES * sizeof(int), s1);
    k_count_out<<<(E / 4 + 255) / 256, 256, 0, s1>>>(src, E);
    cudaEventRecord(evOut, s1);

    // kernels #2,#3: dense prep
    k_prepP<<<N_NEXT / 16, 128, 0, s2>>>(next_h, W_fus, tdw, b_conv, b_fus, conv_w);
    k_packB<<<(NCH_TOT * CHUNK_U32 + 255) / 256, 256, 0, s2>>>(W_conv, conv_w);

    // kernel #4: GEMM (ncu profiles the 4th submitted kernel)
    cudaStreamWaitEvent(s2, evOut, 0);
    k_gemm<<<(N_NODES + 127) / 128, 256, GEMM_SMEM, s2>>>(curr_h, inc);
    cudaEventRecord(evGemm, s2);

    // rest of CSR chain
    cudaMemsetAsync(p_in, 0, N_NODES * sizeof(int), s1);
    k_count_in<<<(E / 4 + 255) / 256, 256, 0, s1>>>(dst, E);
    k_scan_a<<<49, 1024, 0, s1>>>();
    k_scan_b<<<1, 64, 0, s1>>>();
    k_scan_c<<<49, 1024, 0, s1>>>();
    k_fill<<<(E / 4 + 255) / 256, 256, 0, s1>>>(src, dst, E);
    cudaEventRecord(evCsr, s1);

    // join, then gather
    cudaStreamWaitEvent(0, evCsr, 0);
    cudaStreamWaitEvent(0, evGemm, 0);
    k_gather<<<(N_NODES * 32 + 255) / 256, 256>>>(ln_g, ln_b, out);
}